// round 2
// baseline (speedup 1.0000x reference)
#include <cuda_runtime.h>
#include <cuda_bf16.h>
#include <math.h>

// Problem constants (match reference)
#define NN 50000
#define EE 1600000
#define FIN 256
#define HH 128
#define CC 40

// ---------------- device scratch (no allocs allowed) ----------------
__device__ __align__(16) float g_bufA[(size_t)NN * HH];
__device__ __align__(16) float g_bufB[(size_t)NN * HH];
__device__ float g_inv[NN];
__device__ int   g_deg[NN];
__device__ int   g_rowptr[NN + 1];
__device__ int   g_cursor[NN];
__device__ int   g_esrc[EE];
__device__ __align__(16) float g_ewt[EE];
__device__ float g_Wc[CC * CC];      // We @ Wf_top  (40x40)
__device__ float g_cbias[CC];        // bf + be @ Wf_top

// ---------------- row L2 norm (inverse, clamped) ----------------
__global__ void rownorm_kernel(const float* __restrict__ x, int n) {
    int w = (blockIdx.x * blockDim.x + threadIdx.x) >> 5;
    int lane = threadIdx.x & 31;
    if (w >= n) return;
    const float4* p = (const float4*)(x + (size_t)w * FIN);
    float4 a = p[lane];
    float4 b = p[lane + 32];
    float s = a.x*a.x + a.y*a.y + a.z*a.z + a.w*a.w
            + b.x*b.x + b.y*b.y + b.z*b.z + b.w*b.w;
    #pragma unroll
    for (int off = 16; off > 0; off >>= 1) s += __shfl_xor_sync(0xffffffffu, s, off);
    if (lane == 0) g_inv[w] = 1.0f / fmaxf(sqrtf(s), 1e-12f);
}

// ---------------- SGEMM: C[M x 128] = A[M x K] * B[K x 128], optional row scale ----------------
#define BM 128
#define BN 128
#define BK 16
#define TM 8
#define TN 8
template<bool SCALE>
__global__ __launch_bounds__(256) void gemm_kernel(
    const float* __restrict__ A, const float* __restrict__ B,
    float* __restrict__ C, int M, int K)
{
    __shared__ float As[BK][BM];
    __shared__ float Bs[BK][BN];
    int tid = threadIdx.x;
    int m0 = blockIdx.x * BM;
    int tx = tid & 15, ty = tid >> 4;
    float acc[TM][TN];
    #pragma unroll
    for (int i = 0; i < TM; i++)
        #pragma unroll
        for (int j = 0; j < TN; j++) acc[i][j] = 0.0f;

    for (int k0 = 0; k0 < K; k0 += BK) {
        #pragma unroll
        for (int i = 0; i < 2; i++) {
            int idx = tid + i * 256;        // 0..511
            int row = idx >> 2;             // 0..127
            int c4  = idx & 3;              // 0..3
            int gr = m0 + row;
            float4 v = make_float4(0.f, 0.f, 0.f, 0.f);
            if (gr < M) v = *(const float4*)(A + (size_t)gr * K + k0 + c4 * 4);
            As[c4 * 4 + 0][row] = v.x;
            As[c4 * 4 + 1][row] = v.y;
            As[c4 * 4 + 2][row] = v.z;
            As[c4 * 4 + 3][row] = v.w;
        }
        #pragma unroll
        for (int i = 0; i < 2; i++) {
            int idx = tid + i * 256;
            int row = idx >> 5;             // 0..15
            int c4  = idx & 31;
            float4 v = *(const float4*)(B + (size_t)(k0 + row) * BN + c4 * 4);
            *(float4*)&Bs[row][c4 * 4] = v;
        }
        __syncthreads();
        #pragma unroll
        for (int kk = 0; kk < BK; kk++) {
            float ra[TM], rb[TN];
            #pragma unroll
            for (int i = 0; i < TM; i++) ra[i] = As[kk][ty * TM + i];
            #pragma unroll
            for (int j = 0; j < TN; j++) rb[j] = Bs[kk][tx * TN + j];
            #pragma unroll
            for (int i = 0; i < TM; i++)
                #pragma unroll
                for (int j = 0; j < TN; j++) acc[i][j] += ra[i] * rb[j];
        }
        __syncthreads();
    }
    #pragma unroll
    for (int i = 0; i < TM; i++) {
        int gr = m0 + ty * TM + i;
        if (gr >= M) continue;
        float s = SCALE ? g_inv[gr] : 1.0f;
        #pragma unroll
        for (int j = 0; j < TN; j += 4) {
            float4 v;
            v.x = acc[i][j + 0] * s;
            v.y = acc[i][j + 1] * s;
            v.z = acc[i][j + 2] * s;
            v.w = acc[i][j + 3] * s;
            *(float4*)(C + (size_t)gr * BN + tx * TN + j) = v;
        }
    }
}

// ---------------- CSR build ----------------
__global__ void zero_deg_kernel(int n) {
    int i = blockIdx.x * blockDim.x + threadIdx.x;
    if (i < n) g_deg[i] = 0;
}
__global__ void hist_kernel(const int* __restrict__ dst, int e) {
    int i = blockIdx.x * blockDim.x + threadIdx.x;
    if (i < e) atomicAdd(&g_deg[dst[i]], 1);
}
__global__ void scan_kernel(int n) {
    __shared__ int wsum[32];
    __shared__ int s_run;
    int tid = threadIdx.x, lane = tid & 31, wid = tid >> 5;
    if (tid == 0) s_run = 0;
    __syncthreads();
    for (int base = 0; base < n; base += 1024) {
        int idx = base + tid;
        int v = (idx < n) ? g_deg[idx] : 0;
        int inc = v;
        #pragma unroll
        for (int off = 1; off < 32; off <<= 1) {
            int t = __shfl_up_sync(0xffffffffu, inc, off);
            if (lane >= off) inc += t;
        }
        if (lane == 31) wsum[wid] = inc;
        __syncthreads();
        if (wid == 0) {
            int x = wsum[lane];
            #pragma unroll
            for (int off = 1; off < 32; off <<= 1) {
                int t = __shfl_up_sync(0xffffffffu, x, off);
                if (lane >= off) x += t;
            }
            wsum[lane] = x;
        }
        __syncthreads();
        int woff = (wid > 0) ? wsum[wid - 1] : 0;
        int run = s_run;
        int excl = run + woff + inc - v;
        if (idx < n) { g_rowptr[idx] = excl; g_cursor[idx] = excl; }
        __syncthreads();
        if (tid == 0) s_run = run + wsum[31];
        __syncthreads();
    }
    if (threadIdx.x == 0) g_rowptr[n] = s_run;
}
__global__ void scatter_kernel(const int* __restrict__ src, const int* __restrict__ dst,
                               const float* __restrict__ w, int e) {
    int i = blockIdx.x * blockDim.x + threadIdx.x;
    if (i < e) {
        int d = dst[i];
        int pos = atomicAdd(&g_cursor[d], 1);
        g_esrc[pos] = src[i];
        g_ewt[pos]  = w[i];
    }
}

// ---------------- SPMM gather: out[r] = sum_e w*x[src] (+bias, optional relu) ----------------
// Warp per row. Edge (src, w) pairs are lane-loaded coalesced (32 at a time) and
// broadcast via shfl; the 512B x-row loads are the only remaining gather traffic.
template<bool RELU>
__global__ void spmm_kernel(const float* __restrict__ x, float* __restrict__ out,
                            const float* __restrict__ bias, int n)
{
    int w = (blockIdx.x * blockDim.x + threadIdx.x) >> 5;
    int lane = threadIdx.x & 31;
    if (w >= n) return;
    int e0 = g_rowptr[w], e1 = g_rowptr[w + 1];
    float4 bv = ((const float4*)bias)[lane];
    float4 acc = bv;
    const float4* xv = (const float4*)x;

    for (int base = e0; base < e1; base += 32) {
        int rem = e1 - base;
        int cnt = rem < 32 ? rem : 32;
        int   myi = 0;
        float myw = 0.f;
        if (lane < cnt) { myi = g_esrc[base + lane]; myw = g_ewt[base + lane]; }
        int j = 0;
        for (; j + 4 <= cnt; j += 4) {
            int   i0 = __shfl_sync(0xffffffffu, myi, j);
            int   i1 = __shfl_sync(0xffffffffu, myi, j + 1);
            int   i2 = __shfl_sync(0xffffffffu, myi, j + 2);
            int   i3 = __shfl_sync(0xffffffffu, myi, j + 3);
            float w0 = __shfl_sync(0xffffffffu, myw, j);
            float w1 = __shfl_sync(0xffffffffu, myw, j + 1);
            float w2 = __shfl_sync(0xffffffffu, myw, j + 2);
            float w3 = __shfl_sync(0xffffffffu, myw, j + 3);
            float4 v0 = xv[(size_t)i0 * 32 + lane];
            float4 v1 = xv[(size_t)i1 * 32 + lane];
            float4 v2 = xv[(size_t)i2 * 32 + lane];
            float4 v3 = xv[(size_t)i3 * 32 + lane];
            acc.x += w0 * v0.x; acc.y += w0 * v0.y; acc.z += w0 * v0.z; acc.w += w0 * v0.w;
            acc.x += w1 * v1.x; acc.y += w1 * v1.y; acc.z += w1 * v1.z; acc.w += w1 * v1.w;
            acc.x += w2 * v2.x; acc.y += w2 * v2.y; acc.z += w2 * v2.z; acc.w += w2 * v2.w;
            acc.x += w3 * v3.x; acc.y += w3 * v3.y; acc.z += w3 * v3.z; acc.w += w3 * v3.w;
        }
        for (; j < cnt; j++) {
            int   i0 = __shfl_sync(0xffffffffu, myi, j);
            float w0 = __shfl_sync(0xffffffffu, myw, j);
            float4 v0 = xv[(size_t)i0 * 32 + lane];
            acc.x += w0 * v0.x; acc.y += w0 * v0.y; acc.z += w0 * v0.z; acc.w += w0 * v0.w;
        }
    }
    if (RELU) {
        acc.x = fmaxf(acc.x, 0.f); acc.y = fmaxf(acc.y, 0.f);
        acc.z = fmaxf(acc.z, 0.f); acc.w = fmaxf(acc.w, 0.f);
    }
    ((float4*)out)[(size_t)w * 32 + lane] = acc;
}

// ---------------- head weight pre-combine: Wc = We @ Wf[0:128], cbias = bf + be @ Wf[0:128] ----------------
__global__ void wcomb_kernel(const float* __restrict__ We, const float* __restrict__ be,
                             const float* __restrict__ Wf, const float* __restrict__ bf)
{
    int t = blockIdx.x * blockDim.x + threadIdx.x;
    if (t < CC * CC) {
        int i = t / CC, c = t % CC;
        float s = 0.f;
        for (int k = 0; k < HH; k++) s += We[i * HH + k] * Wf[k * CC + c];
        g_Wc[t] = s;
    }
    if (t < CC) {
        float s = bf[t];
        for (int k = 0; k < HH; k++) s += be[k] * Wf[k * CC + t];
        g_cbias[t] = s;
    }
}

// ---------------- fused head: logits = y@Wc + h@Wf_bot + cbias ; softmax ----------------
__global__ __launch_bounds__(128) void head_kernel(
    const float* __restrict__ h, const float* __restrict__ yin,
    const float* __restrict__ Wf, float* __restrict__ out, int n)
{
    __shared__ float sWfb[HH * CC];   // 20480 B
    __shared__ float sWc[CC * CC];    // 6400 B
    __shared__ float sh[32 * HH];     // 16384 B
    __shared__ float sl[32 * CC];     // 5120 B
    __shared__ float smax[32], sinv[32];
    int tid = threadIdx.x;
    int r0 = blockIdx.x * 32;
    int rows = min(32, n - r0);

    for (int i = tid; i < HH * CC; i += 128) sWfb[i] = Wf[HH * CC + i];
    for (int i = tid; i < CC * CC; i += 128) sWc[i] = g_Wc[i];
    for (int i = tid; i < rows * HH; i += 128) sh[i] = h[(size_t)r0 * HH + i];
    __syncthreads();

    int r = tid >> 2, q = tid & 3, c0 = q * 10;
    if (r < rows) {
        float acc[10];
        #pragma unroll
        for (int j = 0; j < 10; j++) acc[j] = g_cbias[c0 + j];
        for (int k = 0; k < HH; k++) {
            float hv = sh[r * HH + k];
            #pragma unroll
            for (int j = 0; j < 10; j++) acc[j] += hv * sWfb[k * CC + c0 + j];
        }
        const float* yr = yin + (size_t)(r0 + r) * CC;
        for (int k = 0; k < CC; k++) {
            float yv = yr[k];
            #pragma unroll
            for (int j = 0; j < 10; j++) acc[j] += yv * sWc[k * CC + c0 + j];
        }
        #pragma unroll
        for (int j = 0; j < 10; j++) sl[r * CC + c0 + j] = acc[j];
    }
    __syncthreads();
    if (tid < 32 && tid < rows) {
        float m = -1e30f;
        for (int c = 0; c < CC; c++) m = fmaxf(m, sl[tid * CC + c]);
        float s = 0.f;
        for (int c = 0; c < CC; c++) s += __expf(sl[tid * CC + c] - m);
        smax[tid] = m;
        sinv[tid] = 1.0f / s;
    }
    __syncthreads();
    int tot = rows * CC;
    for (int i = tid; i < tot; i += 128) {
        int rr = i / CC;
        out[(size_t)r0 * CC + i] = __expf(sl[i] - smax[rr]) * sinv[rr];
    }
}

// ---------------- launch ----------------
extern "C" void kernel_launch(void* const* d_in, const int* in_sizes, int n_in,
                              void* d_out, int out_size)
{
    const float* features = (const float*)d_in[0];
    const int*   src      = (const int*)  d_in[1];
    const int*   dst      = (const int*)  d_in[2];
    const float* ew       = (const float*)d_in[3];
    const float* y        = (const float*)d_in[4];
    const float* W1       = (const float*)d_in[5];
    const float* b1       = (const float*)d_in[6];
    const float* W2       = (const float*)d_in[7];
    const float* b2       = (const float*)d_in[8];
    const float* We       = (const float*)d_in[9];
    const float* be       = (const float*)d_in[10];
    const float* Wf       = (const float*)d_in[11];
    const float* bf       = (const float*)d_in[12];
    float* out = (float*)d_out;

    int n = in_sizes[0] / FIN;     // 50000
    int e = in_sizes[1];           // 1600000

    int warpBlocks = (n + 7) / 8;          // 8 warps per 256-thread block
    int edgeBlocks = (e + 255) / 256;
    int mTiles     = (n + BM - 1) / BM;

    // Launch order chosen so gemm_kernel<true> lands in the ncu-profiled slot
    // (4th launch of this function) while preserving all data dependencies.
    zero_deg_kernel<<<(n + 255) / 256, 256>>>(n);                 // 1
    rownorm_kernel<<<warpBlocks, 256>>>(features, n);             // 2
    hist_kernel<<<edgeBlocks, 256>>>(dst, e);                     // 3
    gemm_kernel<true><<<mTiles, 256>>>(features, W1, g_bufA, n, FIN); // 4  <-- profiled
    scan_kernel<<<1, 1024>>>(n);                                  // 5
    scatter_kernel<<<edgeBlocks, 256>>>(src, dst, ew, e);         // 6

    // layer 1 aggregate + relu
    spmm_kernel<true><<<warpBlocks, 256>>>(g_bufA, g_bufB, b1, n);    // 7
    // layer 2
    gemm_kernel<false><<<mTiles, 256>>>(g_bufB, W2, g_bufA, n, HH);   // 8
    spmm_kernel<false><<<warpBlocks, 256>>>(g_bufA, g_bufB, b2, n);   // 9

    // head
    wcomb_kernel<<<7, 256>>>(We, be, Wf, bf);                     // 10
    head_kernel<<<(n + 31) / 32, 128>>>(g_bufB, y, Wf, out, n);   // 11
}

// round 3
// speedup vs baseline: 1.0096x; 1.0096x over previous
#include <cuda_runtime.h>
#include <cuda_bf16.h>
#include <math.h>

// Problem constants (match reference)
#define NN 50000
#define EE 1600000
#define FIN 256
#define HH 128
#define CC 40

// ---------------- device scratch (no allocs allowed) ----------------
__device__ __align__(16) float g_bufA[(size_t)NN * HH];
__device__ __align__(16) float g_bufB[(size_t)NN * HH];
__device__ float g_inv[NN];
__device__ int   g_deg[NN];
__device__ int   g_rowptr[NN + 1];
__device__ int   g_cursor[NN];
__device__ int   g_esrc[EE];
__device__ __align__(16) float g_ewt[EE];
__device__ float g_Wc[CC * CC];      // We @ Wf_top  (40x40)
__device__ float g_cbias[CC];        // bf + be @ Wf_top

// ---------------- row L2 norm (inverse, clamped) ----------------
__global__ void rownorm_kernel(const float* __restrict__ x, int n) {
    int w = (blockIdx.x * blockDim.x + threadIdx.x) >> 5;
    int lane = threadIdx.x & 31;
    if (w >= n) return;
    const float4* p = (const float4*)(x + (size_t)w * FIN);
    float4 a = p[lane];
    float4 b = p[lane + 32];
    float s = a.x*a.x + a.y*a.y + a.z*a.z + a.w*a.w
            + b.x*b.x + b.y*b.y + b.z*b.z + b.w*b.w;
    #pragma unroll
    for (int off = 16; off > 0; off >>= 1) s += __shfl_xor_sync(0xffffffffu, s, off);
    if (lane == 0) g_inv[w] = 1.0f / fmaxf(sqrtf(s), 1e-12f);
}

// ---------------- SGEMM (double buffered): C[M x 128] tile = A[M x K] * B[K x 128] ----------------
// BM=128 rows, BN=64 cols per block (blockIdx.y in {0,1}), BK=8, 256 threads, TM=8 x TN=4.
#define GBM 128
#define GBN 64
#define GBK 8
template<bool SCALE>
__global__ __launch_bounds__(256, 3) void gemm_kernel(
    const float* __restrict__ A, const float* __restrict__ B,
    float* __restrict__ C, int M, int K)
{
    __shared__ float As[2][GBK][GBM + 4];
    __shared__ float Bs[2][GBK][GBN];
    int tid = threadIdx.x;
    int m0 = blockIdx.x * GBM;
    int n0 = blockIdx.y * GBN;
    int tx = tid & 15, ty = tid >> 4;

    // A stage: each thread loads one float4: row = tid>>1 (0..127), 4-col half = (tid&1)*4
    int arow = tid >> 1;
    int ahalf = (tid & 1) * 4;
    bool aok = (m0 + arow) < M;
    const float* Aptr = A + (size_t)(m0 + arow) * K + ahalf;
    // B stage: each thread loads one float2: row = tid>>5 (0..7), col = (tid&31)*2
    int brow = tid >> 5;
    int bcol = (tid & 31) * 2;
    const float* Bptr = B + (size_t)brow * HH + n0 + bcol;

    float acc[8][4];
    #pragma unroll
    for (int i = 0; i < 8; i++)
        #pragma unroll
        for (int j = 0; j < 4; j++) acc[i][j] = 0.0f;

    float4 areg = make_float4(0.f, 0.f, 0.f, 0.f);
    if (aok) areg = *(const float4*)Aptr;
    float2 breg = *(const float2*)Bptr;

    // store k0=0 into buf 0
    As[0][ahalf + 0][arow] = areg.x;
    As[0][ahalf + 1][arow] = areg.y;
    As[0][ahalf + 2][arow] = areg.z;
    As[0][ahalf + 3][arow] = areg.w;
    Bs[0][brow][bcol] = breg.x;
    Bs[0][brow][bcol + 1] = breg.y;
    __syncthreads();

    int buf = 0;
    for (int k0 = GBK; k0 < K; k0 += GBK) {
        // prefetch next tile (global -> regs), overlapped with compute below
        areg = make_float4(0.f, 0.f, 0.f, 0.f);
        if (aok) areg = *(const float4*)(Aptr + k0);
        breg = *(const float2*)(Bptr + (size_t)k0 * HH);

        #pragma unroll
        for (int kk = 0; kk < GBK; kk++) {
            float ra[8], rb[4];
            *(float4*)(ra)     = *(const float4*)&As[buf][kk][ty * 8];
            *(float4*)(ra + 4) = *(const float4*)&As[buf][kk][ty * 8 + 4];
            *(float4*)(rb)     = *(const float4*)&Bs[buf][kk][tx * 4];
            #pragma unroll
            for (int i = 0; i < 8; i++)
                #pragma unroll
                for (int j = 0; j < 4; j++) acc[i][j] += ra[i] * rb[j];
        }

        int nb = buf ^ 1;
        As[nb][ahalf + 0][arow] = areg.x;
        As[nb][ahalf + 1][arow] = areg.y;
        As[nb][ahalf + 2][arow] = areg.z;
        As[nb][ahalf + 3][arow] = areg.w;
        Bs[nb][brow][bcol] = breg.x;
        Bs[nb][brow][bcol + 1] = breg.y;
        __syncthreads();
        buf = nb;
    }
    // last tile
    #pragma unroll
    for (int kk = 0; kk < GBK; kk++) {
        float ra[8], rb[4];
        *(float4*)(ra)     = *(const float4*)&As[buf][kk][ty * 8];
        *(float4*)(ra + 4) = *(const float4*)&As[buf][kk][ty * 8 + 4];
        *(float4*)(rb)     = *(const float4*)&Bs[buf][kk][tx * 4];
        #pragma unroll
        for (int i = 0; i < 8; i++)
            #pragma unroll
            for (int j = 0; j < 4; j++) acc[i][j] += ra[i] * rb[j];
    }

    #pragma unroll
    for (int i = 0; i < 8; i++) {
        int gr = m0 + ty * 8 + i;
        if (gr >= M) continue;
        float s = SCALE ? g_inv[gr] : 1.0f;
        float4 v;
        v.x = acc[i][0] * s; v.y = acc[i][1] * s;
        v.z = acc[i][2] * s; v.w = acc[i][3] * s;
        *(float4*)(C + (size_t)gr * HH + n0 + tx * 4) = v;
    }
}

// ---------------- CSR build ----------------
__global__ void zero_deg_kernel(int n) {
    int i = blockIdx.x * blockDim.x + threadIdx.x;
    if (i < n) g_deg[i] = 0;
}
__global__ void hist_kernel(const int* __restrict__ dst, int e) {
    int i = blockIdx.x * blockDim.x + threadIdx.x;
    if (i < e) atomicAdd(&g_deg[dst[i]], 1);
}
__global__ void scan_kernel(int n) {
    __shared__ int wsum[32];
    __shared__ int s_run;
    int tid = threadIdx.x, lane = tid & 31, wid = tid >> 5;
    if (tid == 0) s_run = 0;
    __syncthreads();
    for (int base = 0; base < n; base += 1024) {
        int idx = base + tid;
        int v = (idx < n) ? g_deg[idx] : 0;
        int inc = v;
        #pragma unroll
        for (int off = 1; off < 32; off <<= 1) {
            int t = __shfl_up_sync(0xffffffffu, inc, off);
            if (lane >= off) inc += t;
        }
        if (lane == 31) wsum[wid] = inc;
        __syncthreads();
        if (wid == 0) {
            int x = wsum[lane];
            #pragma unroll
            for (int off = 1; off < 32; off <<= 1) {
                int t = __shfl_up_sync(0xffffffffu, x, off);
                if (lane >= off) x += t;
            }
            wsum[lane] = x;
        }
        __syncthreads();
        int woff = (wid > 0) ? wsum[wid - 1] : 0;
        int run = s_run;
        int excl = run + woff + inc - v;
        if (idx < n) { g_rowptr[idx] = excl; g_cursor[idx] = excl; }
        __syncthreads();
        if (tid == 0) s_run = run + wsum[31];
        __syncthreads();
    }
    if (threadIdx.x == 0) g_rowptr[n] = s_run;
}
__global__ void scatter_kernel(const int* __restrict__ src, const int* __restrict__ dst,
                               const float* __restrict__ w, int e) {
    int i = blockIdx.x * blockDim.x + threadIdx.x;
    if (i < e) {
        int d = dst[i];
        int pos = atomicAdd(&g_cursor[d], 1);
        g_esrc[pos] = src[i];
        g_ewt[pos]  = w[i];
    }
}

// ---------------- SPMM gather: out[r] = bias + sum_e w*x[src] (optional relu) ----------------
template<bool RELU>
__global__ void spmm_kernel(const float* __restrict__ x, float* __restrict__ out,
                            const float* __restrict__ bias, int n)
{
    int w = (blockIdx.x * blockDim.x + threadIdx.x) >> 5;
    int lane = threadIdx.x & 31;
    if (w >= n) return;
    int e0 = g_rowptr[w], e1 = g_rowptr[w + 1];
    float4 acc = ((const float4*)bias)[lane];
    const float4* xv = (const float4*)x;

    for (int base = e0; base < e1; base += 32) {
        int rem = e1 - base;
        int cnt = rem < 32 ? rem : 32;
        int   myi = 0;
        float myw = 0.f;
        if (lane < cnt) { myi = g_esrc[base + lane]; myw = g_ewt[base + lane]; }
        int j = 0;
        for (; j + 8 <= cnt; j += 8) {
            int   i0 = __shfl_sync(0xffffffffu, myi, j);
            int   i1 = __shfl_sync(0xffffffffu, myi, j + 1);
            int   i2 = __shfl_sync(0xffffffffu, myi, j + 2);
            int   i3 = __shfl_sync(0xffffffffu, myi, j + 3);
            int   i4 = __shfl_sync(0xffffffffu, myi, j + 4);
            int   i5 = __shfl_sync(0xffffffffu, myi, j + 5);
            int   i6 = __shfl_sync(0xffffffffu, myi, j + 6);
            int   i7 = __shfl_sync(0xffffffffu, myi, j + 7);
            float w0 = __shfl_sync(0xffffffffu, myw, j);
            float w1 = __shfl_sync(0xffffffffu, myw, j + 1);
            float w2 = __shfl_sync(0xffffffffu, myw, j + 2);
            float w3 = __shfl_sync(0xffffffffu, myw, j + 3);
            float w4 = __shfl_sync(0xffffffffu, myw, j + 4);
            float w5 = __shfl_sync(0xffffffffu, myw, j + 5);
            float w6 = __shfl_sync(0xffffffffu, myw, j + 6);
            float w7 = __shfl_sync(0xffffffffu, myw, j + 7);
            float4 v0 = xv[(size_t)i0 * 32 + lane];
            float4 v1 = xv[(size_t)i1 * 32 + lane];
            float4 v2 = xv[(size_t)i2 * 32 + lane];
            float4 v3 = xv[(size_t)i3 * 32 + lane];
            float4 v4 = xv[(size_t)i4 * 32 + lane];
            float4 v5 = xv[(size_t)i5 * 32 + lane];
            float4 v6 = xv[(size_t)i6 * 32 + lane];
            float4 v7 = xv[(size_t)i7 * 32 + lane];
            acc.x += w0 * v0.x; acc.y += w0 * v0.y; acc.z += w0 * v0.z; acc.w += w0 * v0.w;
            acc.x += w1 * v1.x; acc.y += w1 * v1.y; acc.z += w1 * v1.z; acc.w += w1 * v1.w;
            acc.x += w2 * v2.x; acc.y += w2 * v2.y; acc.z += w2 * v2.z; acc.w += w2 * v2.w;
            acc.x += w3 * v3.x; acc.y += w3 * v3.y; acc.z += w3 * v3.z; acc.w += w3 * v3.w;
            acc.x += w4 * v4.x; acc.y += w4 * v4.y; acc.z += w4 * v4.z; acc.w += w4 * v4.w;
            acc.x += w5 * v5.x; acc.y += w5 * v5.y; acc.z += w5 * v5.z; acc.w += w5 * v5.w;
            acc.x += w6 * v6.x; acc.y += w6 * v6.y; acc.z += w6 * v6.z; acc.w += w6 * v6.w;
            acc.x += w7 * v7.x; acc.y += w7 * v7.y; acc.z += w7 * v7.z; acc.w += w7 * v7.w;
        }
        for (; j < cnt; j++) {
            int   i0 = __shfl_sync(0xffffffffu, myi, j);
            float w0 = __shfl_sync(0xffffffffu, myw, j);
            float4 v0 = xv[(size_t)i0 * 32 + lane];
            acc.x += w0 * v0.x; acc.y += w0 * v0.y; acc.z += w0 * v0.z; acc.w += w0 * v0.w;
        }
    }
    if (RELU) {
        acc.x = fmaxf(acc.x, 0.f); acc.y = fmaxf(acc.y, 0.f);
        acc.z = fmaxf(acc.z, 0.f); acc.w = fmaxf(acc.w, 0.f);
    }
    ((float4*)out)[(size_t)w * 32 + lane] = acc;
}

// ---------------- head weight pre-combine: Wc = We @ Wf[0:128], cbias = bf + be @ Wf[0:128] ----------------
__global__ void wcomb_kernel(const float* __restrict__ We, const float* __restrict__ be,
                             const float* __restrict__ Wf, const float* __restrict__ bf)
{
    int t = blockIdx.x * blockDim.x + threadIdx.x;
    if (t < CC * CC) {
        int i = t / CC, c = t % CC;
        float s = 0.f;
        for (int k = 0; k < HH; k++) s += We[i * HH + k] * Wf[k * CC + c];
        g_Wc[t] = s;
    }
    if (t < CC) {
        float s = bf[t];
        for (int k = 0; k < HH; k++) s += be[k] * Wf[k * CC + t];
        g_cbias[t] = s;
    }
}

// ---------------- fused head: logits = y@Wc + h@Wf_bot + cbias ; softmax ----------------
__global__ __launch_bounds__(128) void head_kernel(
    const float* __restrict__ h, const float* __restrict__ yin,
    const float* __restrict__ Wf, float* __restrict__ out, int n)
{
    __shared__ float sWfb[HH * CC];
    __shared__ float sWc[CC * CC];
    __shared__ float sh[32 * HH];
    __shared__ float sl[32 * CC];
    __shared__ float smax[32], sinv[32];
    int tid = threadIdx.x;
    int r0 = blockIdx.x * 32;
    int rows = min(32, n - r0);

    for (int i = tid; i < HH * CC; i += 128) sWfb[i] = Wf[HH * CC + i];
    for (int i = tid; i < CC * CC; i += 128) sWc[i] = g_Wc[i];
    for (int i = tid; i < rows * HH; i += 128) sh[i] = h[(size_t)r0 * HH + i];
    __syncthreads();

    int r = tid >> 2, q = tid & 3, c0 = q * 10;
    if (r < rows) {
        float acc[10];
        #pragma unroll
        for (int j = 0; j < 10; j++) acc[j] = g_cbias[c0 + j];
        for (int k = 0; k < HH; k++) {
            float hv = sh[r * HH + k];
            #pragma unroll
            for (int j = 0; j < 10; j++) acc[j] += hv * sWfb[k * CC + c0 + j];
        }
        const float* yr = yin + (size_t)(r0 + r) * CC;
        for (int k = 0; k < CC; k++) {
            float yv = yr[k];
            #pragma unroll
            for (int j = 0; j < 10; j++) acc[j] += yv * sWc[k * CC + c0 + j];
        }
        #pragma unroll
        for (int j = 0; j < 10; j++) sl[r * CC + c0 + j] = acc[j];
    }
    __syncthreads();
    if (tid < 32 && tid < rows) {
        float m = -1e30f;
        for (int c = 0; c < CC; c++) m = fmaxf(m, sl[tid * CC + c]);
        float s = 0.f;
        for (int c = 0; c < CC; c++) s += __expf(sl[tid * CC + c] - m);
        smax[tid] = m;
        sinv[tid] = 1.0f / s;
    }
    __syncthreads();
    int tot = rows * CC;
    for (int i = tid; i < tot; i += 128) {
        int rr = i / CC;
        out[(size_t)r0 * CC + i] = __expf(sl[i] - smax[rr]) * sinv[rr];
    }
}

// ---------------- launch ----------------
extern "C" void kernel_launch(void* const* d_in, const int* in_sizes, int n_in,
                              void* d_out, int out_size)
{
    const float* features = (const float*)d_in[0];
    const int*   src      = (const int*)  d_in[1];
    const int*   dst      = (const int*)  d_in[2];
    const float* ew       = (const float*)d_in[3];
    const float* y        = (const float*)d_in[4];
    const float* W1       = (const float*)d_in[5];
    const float* b1       = (const float*)d_in[6];
    const float* W2       = (const float*)d_in[7];
    const float* b2       = (const float*)d_in[8];
    const float* We       = (const float*)d_in[9];
    const float* be       = (const float*)d_in[10];
    const float* Wf       = (const float*)d_in[11];
    const float* bf       = (const float*)d_in[12];
    float* out = (float*)d_out;

    int n = in_sizes[0] / FIN;     // 50000
    int e = in_sizes[1];           // 1600000

    int warpBlocks = (n + 7) / 8;          // 8 warps per 256-thread block
    int edgeBlocks = (e + 255) / 256;
    dim3 gemmGrid((n + GBM - 1) / GBM, HH / GBN);

    // Order: slot 4 (= ncu-profiled launch) is scatter_kernel this round.
    zero_deg_kernel<<<(n + 255) / 256, 256>>>(n);                      // 1
    hist_kernel<<<edgeBlocks, 256>>>(dst, e);                          // 2
    scan_kernel<<<1, 1024>>>(n);                                       // 3
    scatter_kernel<<<edgeBlocks, 256>>>(src, dst, ew, e);              // 4  <-- profiled
    rownorm_kernel<<<warpBlocks, 256>>>(features, n);                  // 5
    gemm_kernel<true><<<gemmGrid, 256>>>(features, W1, g_bufA, n, FIN);// 6

    spmm_kernel<true><<<warpBlocks, 256>>>(g_bufA, g_bufB, b1, n);     // 7
    gemm_kernel<false><<<gemmGrid, 256>>>(g_bufB, W2, g_bufA, n, HH);  // 8
    spmm_kernel<false><<<warpBlocks, 256>>>(g_bufA, g_bufB, b2, n);    // 9

    wcomb_kernel<<<7, 256>>>(We, be, Wf, bf);                          // 10
    head_kernel<<<(n + 31) / 32, 128>>>(g_bufB, y, Wf, out, n);        // 11
}